// round 13
// baseline (speedup 1.0000x reference)
#include <cuda_runtime.h>
#include <cuda_bf16.h>
#include <cuda_fp16.h>
#include <math.h>
#include <cstdint>

#define N_MAX 100000
#define E_MAX 1600000
#define F0 256
#define F1 128
#define F2 16

// ---------------- scratch (static device globals; no allocation) ------------
__device__ int      g_deg[N_MAX];
__device__ int      g_rowptr[N_MAX + 1];
__device__ int      g_cursor[N_MAX];
__device__ int      g_csr[E_MAX];
__device__ unsigned g_h1h[(size_t)N_MAX * F1 / 2];  // h1 as half2 pairs
__device__ float    g_h2[(size_t)N_MAX * F2];
__device__ int      g_bsums[64];
// W1 split bf16 hi/lo, chunked [16 kchunks][128 n][8 uints (16 k bf16)]
__device__ uint32_t g_Wh[16 * 128 * 8];
__device__ uint32_t g_Wl[16 * 128 * 8];

// ---------------- helpers ----------------------------------------------------
__device__ __forceinline__ unsigned smem_u32(const void* p) {
    unsigned r;
    asm("{ .reg .u64 t; cvta.to.shared.u64 t, %1; cvt.u32.u64 %0, t; }"
        : "=r"(r) : "l"(p));
    return r;
}
__device__ __forceinline__ void cp_async16(unsigned dst, const void* src) {
    asm volatile("cp.async.ca.shared.global [%0], [%1], 16;"
                 :: "r"(dst), "l"(src));
}
__device__ __forceinline__ void cp_commit() { asm volatile("cp.async.commit_group;"); }
__device__ __forceinline__ void cp_wait0()  { asm volatile("cp.async.wait_group 0;"); }
__device__ __forceinline__ unsigned pack_h2(float a, float b) {
    __half2 h = __floats2half2_rn(a, b);
    return *(unsigned*)&h;
}
__device__ __forceinline__ void ldmx4(uint32_t* r, unsigned addr) {
    asm volatile("ldmatrix.sync.aligned.m8n8.x4.shared.b16 {%0,%1,%2,%3}, [%4];"
                 : "=r"(r[0]), "=r"(r[1]), "=r"(r[2]), "=r"(r[3]) : "r"(addr));
}
__device__ __forceinline__ void ldmx2(uint32_t* r, unsigned addr) {
    asm volatile("ldmatrix.sync.aligned.m8n8.x2.shared.b16 {%0,%1}, [%2];"
                 : "=r"(r[0]), "=r"(r[1]) : "r"(addr));
}
__device__ __forceinline__ void mma_bf16(float* d, const uint32_t* a, const uint32_t* b) {
    asm volatile(
        "mma.sync.aligned.m16n8k16.row.col.f32.bf16.bf16.f32 "
        "{%0,%1,%2,%3}, {%4,%5,%6,%7}, {%8,%9}, {%0,%1,%2,%3};"
        : "+f"(d[0]), "+f"(d[1]), "+f"(d[2]), "+f"(d[3])
        : "r"(a[0]), "r"(a[1]), "r"(a[2]), "r"(a[3]), "r"(b[0]), "r"(b[1]));
}
__device__ __forceinline__ uint32_t bfpair(float a, float b) {
    union { __nv_bfloat162 v; uint32_t u; } u;
    u.v = __nv_bfloat162(__float2bfloat16(a), __float2bfloat16(b));
    return u.u;
}
__device__ __forceinline__ float dinv_of(int i) {
    return rsqrtf((float)(g_deg[i] + 1));
}
__device__ __forceinline__ void addh2(float4& acc, uint2 u) {
    float2 a = __half22float2(*(__half2*)&u.x);
    float2 b = __half22float2(*(__half2*)&u.y);
    acc.x += a.x; acc.y += a.y; acc.z += b.x; acc.w += b.y;
}

// ---------------- small kernels ----------------------------------------------
__global__ void k_zero(int n) {
    int i = blockIdx.x * blockDim.x + threadIdx.x;
    if (i < n) g_deg[i] = 0;
}
__global__ void k_deg(const int* __restrict__ ei, int E, int n) {
    int i = blockIdx.x * blockDim.x + threadIdx.x;
    if (i < E) {
        int dst = ei[E + i];
        if ((unsigned)dst < (unsigned)n) atomicAdd(&g_deg[dst], 1);
    }
}

// W1 [256][128] fp32 -> chunked hi/lo bf16 [c][n][8u]
__global__ void k_prepw(const float* __restrict__ W) {
    int idx = blockIdx.x * blockDim.x + threadIdx.x;
    if (idx >= 16 * 128) return;
    int c = idx >> 7;
    int nn = idx & 127;
    uint32_t hu[8], lu[8];
#pragma unroll
    for (int p = 0; p < 8; p++) {
        float v0 = W[(size_t)(c * 16 + 2 * p) * F1 + nn];
        float v1 = W[(size_t)(c * 16 + 2 * p + 1) * F1 + nn];
        __nv_bfloat16 h0 = __float2bfloat16(v0);
        __nv_bfloat16 h1 = __float2bfloat16(v1);
        hu[p] = bfpair(__bfloat162float(h0), __bfloat162float(h1));
        lu[p] = bfpair(v0 - __bfloat162float(h0), v1 - __bfloat162float(h1));
    }
    uint32_t* dh = g_Wh + (size_t)idx * 8;
    uint32_t* dl = g_Wl + (size_t)idx * 8;
    *(uint4*)(dh)     = make_uint4(hu[0], hu[1], hu[2], hu[3]);
    *(uint4*)(dh + 4) = make_uint4(hu[4], hu[5], hu[6], hu[7]);
    *(uint4*)(dl)     = make_uint4(lu[0], lu[1], lu[2], lu[3]);
    *(uint4*)(dl + 4) = make_uint4(lu[4], lu[5], lu[6], lu[7]);
}

// ---------------- scan + CSR -------------------------------------------------
__global__ void k_scan1(int n) {
    __shared__ int warpsum[8];
    int base = blockIdx.x * 4096;
    int t0 = base + threadIdx.x * 16;
    int vals[16];
    int s = 0;
#pragma unroll
    for (int j = 0; j < 16; j++) {
        int idx = t0 + j;
        int v = (idx < n) ? g_deg[idx] : 0;
        vals[j] = s;
        s += v;
    }
    int lane = threadIdx.x & 31, w = threadIdx.x >> 5;
    int x = s;
#pragma unroll
    for (int d = 1; d < 32; d <<= 1) {
        int y = __shfl_up_sync(0xffffffffu, x, d);
        if (lane >= d) x += y;
    }
    if (lane == 31) warpsum[w] = x;
    __syncthreads();
    if (w == 0 && lane < 8) {
        int y = warpsum[lane];
#pragma unroll
        for (int d = 1; d < 8; d <<= 1) {
            int z = __shfl_up_sync(0xffu, y, d);
            if (lane >= d) y += z;
        }
        warpsum[lane] = y;
    }
    __syncthreads();
    int warpoff = (w > 0) ? warpsum[w - 1] : 0;
    int throff = warpoff + x - s;
#pragma unroll
    for (int j = 0; j < 16; j++) {
        int idx = t0 + j;
        if (idx < n) g_rowptr[idx] = throff + vals[j];
    }
    if (threadIdx.x == 255) g_bsums[blockIdx.x] = warpoff + x;
}
__global__ void k_scan2(int nb) {
    if (threadIdx.x == 0 && blockIdx.x == 0) {
        int s = 0;
        for (int i = 0; i < nb; i++) { int v = g_bsums[i]; g_bsums[i] = s; s += v; }
    }
}
__global__ void k_scan3(int n, int E) {
    int i = blockIdx.x * blockDim.x + threadIdx.x;
    if (i < n) {
        int r = g_rowptr[i] + g_bsums[i >> 12];
        g_rowptr[i] = r;
        g_cursor[i] = r;
    }
    if (i == 0) g_rowptr[n] = E;
}
__global__ void k_fill(const int* __restrict__ ei, int E, int n) {
    int i = blockIdx.x * blockDim.x + threadIdx.x;
    if (i < E) {
        int dst = ei[E + i];
        int src = ei[i];
        if ((unsigned)dst < (unsigned)n && (unsigned)src < (unsigned)n) {
            int pos = atomicAdd(&g_cursor[dst], 1);
            g_csr[pos] = src;
        }
    }
}

// ---------------- GEMM1 via mma.sync bf16 3-split, streamed B ----------------
#define A_ROW  48
#define ASZ    6144
#define B_ROW  48
#define BCH    6144
#define SM_TOTAL (4*BCH + 4*ASZ)    /* 49152 */

__global__ void __launch_bounds__(256) k_gemm1(const float* __restrict__ X, int M) {
    extern __shared__ char sm[];
    unsigned sb = smem_u32(sm);
    const unsigned BsH = sb, BsL = sb + 2 * BCH, Ah = sb + 4 * BCH, Al = Ah + 2 * ASZ;

    int tid = threadIdx.x, lane = tid & 31, wid = tid >> 5;
    int wm = wid >> 2, wn = wid & 3;
    int m0 = blockIdx.x * 128;

    float acc[4][4][4];
#pragma unroll
    for (int i = 0; i < 4; i++)
#pragma unroll
        for (int j = 0; j < 4; j++)
#pragma unroll
            for (int q = 0; q < 4; q++) acc[i][j][q] = 0.f;

    int mrow = tid >> 1, khalf = tid & 1;
    int gm = m0 + mrow;
    bool ok = gm < M;
    const float4 z4 = make_float4(0.f, 0.f, 0.f, 0.f);
    const float* xrow = X + (size_t)gm * F0 + khalf * 8;

    int br = tid >> 1, bh = tid & 1;
    const uint32_t* srcH = g_Wh + (size_t)br * 8 + bh * 4;
    const uint32_t* srcL = g_Wl + (size_t)br * 8 + bh * 4;
    unsigned dstB = (unsigned)(br * B_ROW + bh * 16);

    cp_async16(BsH + dstB, srcH);
    cp_async16(BsL + dstB, srcL);
    cp_commit();
    {
        float4 va = ok ? *(const float4*)(xrow)     : z4;
        float4 vb = ok ? *(const float4*)(xrow + 4) : z4;
        float vf[8] = {va.x, va.y, va.z, va.w, vb.x, vb.y, vb.z, vb.w};
        uint32_t hu[4], lu[4];
#pragma unroll
        for (int p = 0; p < 4; p++) {
            float a = vf[2 * p], b = vf[2 * p + 1];
            __nv_bfloat16 ha = __float2bfloat16(a), hb = __float2bfloat16(b);
            hu[p] = bfpair(__bfloat162float(ha), __bfloat162float(hb));
            lu[p] = bfpair(a - __bfloat162float(ha), b - __bfloat162float(hb));
        }
        size_t off = (size_t)(4 * BCH) + mrow * A_ROW + khalf * 16;
        *(uint4*)(sm + off)           = make_uint4(hu[0], hu[1], hu[2], hu[3]);
        *(uint4*)(sm + off + 2 * ASZ) = make_uint4(lu[0], lu[1], lu[2], lu[3]);
    }
    cp_wait0();
    __syncthreads();

    int arow = (lane & 7) + ((lane >> 3) & 1) * 8;
    int acol = ((lane >> 4) & 1) * 16;
    int brow = lane & 7;
    int bsel = ((lane >> 3) & 1) * 16;

#pragma unroll 1
    for (int it = 0; it < 16; it++) {
        int cur = it & 1, nxt = cur ^ 1;
        float4 na = z4, nb = z4;
        if (it < 15) {
            size_t cofs = (size_t)(it + 1) * 128 * 8;
            cp_async16(BsH + nxt * BCH + dstB, srcH + cofs);
            cp_async16(BsL + nxt * BCH + dstB, srcL + cofs);
            cp_commit();
            const float* xc = xrow + (it + 1) * 16;
            na = ok ? *(const float4*)(xc)     : z4;
            nb = ok ? *(const float4*)(xc + 4) : z4;
        }
        unsigned AhB = Ah + cur * ASZ, AlB = Al + cur * ASZ;
        unsigned BhB = BsH + cur * BCH, BlB = BsL + cur * BCH;
        uint32_t ah[4][4], al[4][4], bhf[4][2], blf[4][2];
#pragma unroll
        for (int ti = 0; ti < 4; ti++) {
            unsigned o = (wm * 64 + ti * 16 + arow) * A_ROW + acol;
            ldmx4(ah[ti], AhB + o);
            ldmx4(al[ti], AlB + o);
        }
#pragma unroll
        for (int tj = 0; tj < 4; tj++) {
            unsigned o = (wn * 32 + tj * 8 + brow) * B_ROW + bsel;
            ldmx2(bhf[tj], BhB + o);
            ldmx2(blf[tj], BlB + o);
        }
#pragma unroll
        for (int ti = 0; ti < 4; ti++)
#pragma unroll
            for (int tj = 0; tj < 4; tj++) {
                mma_bf16(acc[ti][tj], ah[ti], bhf[tj]);
                mma_bf16(acc[ti][tj], ah[ti], blf[tj]);
                mma_bf16(acc[ti][tj], al[ti], bhf[tj]);
            }
        if (it < 15) {
            float vf[8] = {na.x, na.y, na.z, na.w, nb.x, nb.y, nb.z, nb.w};
            uint32_t hu[4], lu[4];
#pragma unroll
            for (int p = 0; p < 4; p++) {
                float a = vf[2 * p], b = vf[2 * p + 1];
                __nv_bfloat16 ha = __float2bfloat16(a), hb = __float2bfloat16(b);
                hu[p] = bfpair(__bfloat162float(ha), __bfloat162float(hb));
                lu[p] = bfpair(a - __bfloat162float(ha), b - __bfloat162float(hb));
            }
            size_t off = (size_t)(4 * BCH) + nxt * ASZ + mrow * A_ROW + khalf * 16;
            *(uint4*)(sm + off)           = make_uint4(hu[0], hu[1], hu[2], hu[3]);
            *(uint4*)(sm + off + 2 * ASZ) = make_uint4(lu[0], lu[1], lu[2], lu[3]);
            cp_wait0();
        }
        __syncthreads();
    }

#pragma unroll
    for (int ti = 0; ti < 4; ti++) {
#pragma unroll
        for (int tj = 0; tj < 4; tj++) {
            int mA = wm * 64 + ti * 16 + (lane >> 2);
            int nn = wn * 32 + tj * 8 + (lane & 3) * 2;
            int r0 = m0 + mA, r1 = r0 + 8;
            if (r0 < M) {
                float s = dinv_of(r0);
                g_h1h[(size_t)r0 * 64 + (nn >> 1)] =
                    pack_h2(acc[ti][tj][0] * s, acc[ti][tj][1] * s);
            }
            if (r1 < M) {
                float s = dinv_of(r1);
                g_h1h[(size_t)r1 * 64 + (nn >> 1)] =
                    pack_h2(acc[ti][tj][2] * s, acc[ti][tj][3] * s);
            }
        }
    }
}

// ---------------- Agg1 (half2 gather, MLP-4, fp32 accum) + fused GEMM2 -------
__global__ void __launch_bounds__(256) k_agg1(
    const float* __restrict__ b1, const float* __restrict__ W2, int n) {
    __shared__ float Wt[F2][F1];
    for (int idx = threadIdx.x; idx < (F1 * F2) / 4; idx += 256) {
        int k = idx >> 2;
        int q4 = (idx & 3) * 4;
        float4 v = *(const float4*)(W2 + (size_t)k * F2 + q4);
        Wt[q4 + 0][k] = v.x;
        Wt[q4 + 1][k] = v.y;
        Wt[q4 + 2][k] = v.z;
        Wt[q4 + 3][k] = v.w;
    }
    __syncthreads();

    int warp = (blockIdx.x * blockDim.x + threadIdx.x) >> 5;
    int lane = threadIdx.x & 31;
    if (warp >= n) return;
    int i = warp;
    int beg = g_rowptr[i], end = g_rowptr[i + 1];
    const unsigned* hs = g_h1h;
    float4 a0, a1, a2, a3;
    a1 = a2 = a3 = make_float4(0.f, 0.f, 0.f, 0.f);
    a0 = a1;
    addh2(a0, *(const uint2*)(hs + (size_t)i * 64 + lane * 2));  // self loop
    for (int e = beg; e < end; e += 32) {
        int cnt = min(32, end - e);
        int j = (e + lane < end) ? g_csr[e + lane] : 0;
        int t = 0;
        for (; t + 3 < cnt; t += 4) {
            int j0 = __shfl_sync(0xffffffffu, j, t);
            int j1 = __shfl_sync(0xffffffffu, j, t + 1);
            int j2 = __shfl_sync(0xffffffffu, j, t + 2);
            int j3 = __shfl_sync(0xffffffffu, j, t + 3);
            uint2 u0 = *(const uint2*)(hs + (size_t)j0 * 64 + lane * 2);
            uint2 u1 = *(const uint2*)(hs + (size_t)j1 * 64 + lane * 2);
            uint2 u2 = *(const uint2*)(hs + (size_t)j2 * 64 + lane * 2);
            uint2 u3 = *(const uint2*)(hs + (size_t)j3 * 64 + lane * 2);
            addh2(a0, u0); addh2(a1, u1); addh2(a2, u2); addh2(a3, u3);
        }
        for (; t < cnt; t++) {
            int j0 = __shfl_sync(0xffffffffu, j, t);
            addh2(a0, *(const uint2*)(hs + (size_t)j0 * 64 + lane * 2));
        }
    }
    float s = dinv_of(i);
    float4 bb = *(const float4*)(b1 + lane * 4);
    float f[4];
    f[0] = fmaxf(fmaf(a0.x + a1.x + a2.x + a3.x, s, bb.x), 0.f);
    f[1] = fmaxf(fmaf(a0.y + a1.y + a2.y + a3.y, s, bb.y), 0.f);
    f[2] = fmaxf(fmaf(a0.z + a1.z + a2.z + a3.z, s, bb.z), 0.f);
    f[3] = fmaxf(fmaf(a0.w + a1.w + a2.w + a3.w, s, bb.w), 0.f);

    float p[F2];
#pragma unroll
    for (int q = 0; q < F2; q++) {
        float4 w = *(const float4*)(&Wt[q][lane * 4]);
        p[q] = f[0] * w.x + f[1] * w.y + f[2] * w.z + f[3] * w.w;
    }
#pragma unroll
    for (int d = 16; d >= 1; d >>= 1) {
#pragma unroll
        for (int q = 0; q < F2; q++)
            p[q] += __shfl_xor_sync(0xffffffffu, p[q], d);
    }
    if (lane < 4) {
        float4 v = make_float4(p[lane * 4] * s, p[lane * 4 + 1] * s,
                               p[lane * 4 + 2] * s, p[lane * 4 + 3] * s);
        *(float4*)(g_h2 + (size_t)i * F2 + lane * 4) = v;
    }
}

// ---------------- Agg2: 4 threads/node, 16 dims, MLP-2, + b2 ----------------
__global__ void k_agg2(const float* __restrict__ b2, float* __restrict__ out, int n) {
    int gt = blockIdx.x * blockDim.x + threadIdx.x;
    int i = gt >> 2;
    if (i >= n) return;
    int q = (gt & 3) * 4;
    int beg = g_rowptr[i], end = g_rowptr[i + 1];
    const float* hs = g_h2;
    float4 acc0 = *(const float4*)(hs + (size_t)i * F2 + q);
    float4 acc1 = make_float4(0.f, 0.f, 0.f, 0.f);
    int e = beg;
    for (; e + 1 < end; e += 2) {
        int j0 = g_csr[e], j1 = g_csr[e + 1];
        float4 v0 = *(const float4*)(hs + (size_t)j0 * F2 + q);
        float4 v1 = *(const float4*)(hs + (size_t)j1 * F2 + q);
        acc0.x += v0.x; acc0.y += v0.y; acc0.z += v0.z; acc0.w += v0.w;
        acc1.x += v1.x; acc1.y += v1.y; acc1.z += v1.z; acc1.w += v1.w;
    }
    if (e < end) {
        int j0 = g_csr[e];
        float4 v0 = *(const float4*)(hs + (size_t)j0 * F2 + q);
        acc0.x += v0.x; acc0.y += v0.y; acc0.z += v0.z; acc0.w += v0.w;
    }
    float s = dinv_of(i);
    float4 bb = *(const float4*)(b2 + q);
    float4 r = make_float4(fmaf(acc0.x + acc1.x, s, bb.x),
                           fmaf(acc0.y + acc1.y, s, bb.y),
                           fmaf(acc0.z + acc1.z, s, bb.z),
                           fmaf(acc0.w + acc1.w, s, bb.w));
    *(float4*)(out + (size_t)i * F2 + q) = r;
}

// ---------------- launch: fork/join graph ------------------------------------
extern "C" void kernel_launch(void* const* d_in, const int* in_sizes, int n_in,
                              void* d_out, int out_size) {
    const float* x  = (const float*)d_in[0];
    const int*   ei = (const int*)d_in[1];
    const float* W1 = (const float*)d_in[2];
    const float* b1 = (const float*)d_in[3];
    const float* W2 = (const float*)d_in[4];
    const float* b2 = (const float*)d_in[5];
    float* out = (float*)d_out;

    int n = in_sizes[0] / F0;       // 100000
    int E = in_sizes[1] / 2;        // 1600000

    static cudaStream_t s2 = 0;
    static cudaEvent_t evFork = 0, evJoin = 0;
    if (!s2) {
        cudaStreamCreateWithFlags(&s2, cudaStreamNonBlocking);
        cudaEventCreateWithFlags(&evFork, cudaEventDisableTiming);
        cudaEventCreateWithFlags(&evJoin, cudaEventDisableTiming);
        cudaFuncSetAttribute(k_gemm1, cudaFuncAttributeMaxDynamicSharedMemorySize,
                             SM_TOTAL);
    }

    int tb = 256;
    k_prepw<<<8, 256>>>(W1);
    k_zero<<<(n + tb - 1) / tb, tb>>>(n);
    k_deg<<<(E + tb - 1) / tb, tb>>>(ei, E, n);

    cudaEventRecord(evFork, 0);
    cudaStreamWaitEvent(s2, evFork, 0);

    k_gemm1<<<(n + 127) / 128, 256, SM_TOTAL>>>(x, n);   // launch 4 (sampled)

    int nb = (n + 4095) / 4096;
    k_scan1<<<nb, 256, 0, s2>>>(n);
    k_scan2<<<1, 32, 0, s2>>>(nb);
    k_scan3<<<(n + tb - 1) / tb, tb, 0, s2>>>(n, E);
    k_fill<<<(E + tb - 1) / tb, tb, 0, s2>>>(ei, E, n);
    cudaEventRecord(evJoin, s2);

    cudaStreamWaitEvent(0, evJoin, 0);
    k_agg1<<<(n * 32 + tb - 1) / tb, tb>>>(b1, W2, n);
    k_agg2<<<(n * 4 + tb - 1) / tb, tb>>>(b2, out, n);
}

// round 14
// speedup vs baseline: 1.0119x; 1.0119x over previous
#include <cuda_runtime.h>
#include <cuda_bf16.h>
#include <cuda_fp16.h>
#include <math.h>
#include <cstdint>

#define N_MAX 100000
#define E_MAX 1600000
#define F0 256
#define F1 128
#define F2 16

// ---------------- scratch (static device globals; no allocation) ------------
__device__ int      g_deg[N_MAX];
__device__ int      g_rowptr[N_MAX + 1];
__device__ int      g_cursor[N_MAX];
__device__ int      g_csr[E_MAX];
__device__ unsigned g_h1h[(size_t)N_MAX * F1 / 2];  // h1 as half2 pairs
__device__ float    g_h2[(size_t)N_MAX * F2];
__device__ int      g_bsums[64];
// W1 split bf16 hi/lo, chunked [16 kchunks][128 n][8 uints (16 k bf16)]
__device__ uint32_t g_Wh[16 * 128 * 8];
__device__ uint32_t g_Wl[16 * 128 * 8];

// ---------------- helpers ----------------------------------------------------
__device__ __forceinline__ unsigned smem_u32(const void* p) {
    unsigned r;
    asm("{ .reg .u64 t; cvta.to.shared.u64 t, %1; cvt.u32.u64 %0, t; }"
        : "=r"(r) : "l"(p));
    return r;
}
__device__ __forceinline__ void cp_async16(unsigned dst, const void* src) {
    asm volatile("cp.async.ca.shared.global [%0], [%1], 16;"
                 :: "r"(dst), "l"(src));
}
__device__ __forceinline__ void cp_commit() { asm volatile("cp.async.commit_group;"); }
__device__ __forceinline__ void cp_wait0()  { asm volatile("cp.async.wait_group 0;"); }
__device__ __forceinline__ void cp_wait1()  { asm volatile("cp.async.wait_group 1;"); }
__device__ __forceinline__ void cp_wait2()  { asm volatile("cp.async.wait_group 2;"); }
__device__ __forceinline__ unsigned pack_h2(float a, float b) {
    __half2 h = __floats2half2_rn(a, b);
    return *(unsigned*)&h;
}
__device__ __forceinline__ void ldmx4(uint32_t* r, unsigned addr) {
    asm volatile("ldmatrix.sync.aligned.m8n8.x4.shared.b16 {%0,%1,%2,%3}, [%4];"
                 : "=r"(r[0]), "=r"(r[1]), "=r"(r[2]), "=r"(r[3]) : "r"(addr));
}
__device__ __forceinline__ void ldmx2(uint32_t* r, unsigned addr) {
    asm volatile("ldmatrix.sync.aligned.m8n8.x2.shared.b16 {%0,%1}, [%2];"
                 : "=r"(r[0]), "=r"(r[1]) : "r"(addr));
}
__device__ __forceinline__ void mma_bf16(float* d, const uint32_t* a, const uint32_t* b) {
    asm volatile(
        "mma.sync.aligned.m16n8k16.row.col.f32.bf16.bf16.f32 "
        "{%0,%1,%2,%3}, {%4,%5,%6,%7}, {%8,%9}, {%0,%1,%2,%3};"
        : "+f"(d[0]), "+f"(d[1]), "+f"(d[2]), "+f"(d[3])
        : "r"(a[0]), "r"(a[1]), "r"(a[2]), "r"(a[3]), "r"(b[0]), "r"(b[1]));
}
__device__ __forceinline__ uint32_t bfpair(float a, float b) {
    union { __nv_bfloat162 v; uint32_t u; } u;
    u.v = __nv_bfloat162(__float2bfloat16(a), __float2bfloat16(b));
    return u.u;
}
__device__ __forceinline__ float dinv_of(int i) {
    return rsqrtf((float)(g_deg[i] + 1));
}

// ---------------- small kernels ----------------------------------------------
__global__ void k_zero(int n) {
    int i = blockIdx.x * blockDim.x + threadIdx.x;
    if (i < n) g_deg[i] = 0;
}
__global__ void k_deg(const int* __restrict__ ei, int E, int n) {
    int i = blockIdx.x * blockDim.x + threadIdx.x;
    if (i < E) {
        int dst = ei[E + i];
        if ((unsigned)dst < (unsigned)n) atomicAdd(&g_deg[dst], 1);
    }
}

// W1 [256][128] fp32 -> chunked hi/lo bf16 [c][n][8u]
__global__ void k_prepw(const float* __restrict__ W) {
    int idx = blockIdx.x * blockDim.x + threadIdx.x;
    if (idx >= 16 * 128) return;
    int c = idx >> 7;
    int nn = idx & 127;
    uint32_t hu[8], lu[8];
#pragma unroll
    for (int p = 0; p < 8; p++) {
        float v0 = W[(size_t)(c * 16 + 2 * p) * F1 + nn];
        float v1 = W[(size_t)(c * 16 + 2 * p + 1) * F1 + nn];
        __nv_bfloat16 h0 = __float2bfloat16(v0);
        __nv_bfloat16 h1 = __float2bfloat16(v1);
        hu[p] = bfpair(__bfloat162float(h0), __bfloat162float(h1));
        lu[p] = bfpair(v0 - __bfloat162float(h0), v1 - __bfloat162float(h1));
    }
    uint32_t* dh = g_Wh + (size_t)idx * 8;
    uint32_t* dl = g_Wl + (size_t)idx * 8;
    *(uint4*)(dh)     = make_uint4(hu[0], hu[1], hu[2], hu[3]);
    *(uint4*)(dh + 4) = make_uint4(hu[4], hu[5], hu[6], hu[7]);
    *(uint4*)(dl)     = make_uint4(lu[0], lu[1], lu[2], lu[3]);
    *(uint4*)(dl + 4) = make_uint4(lu[4], lu[5], lu[6], lu[7]);
}

// ---------------- scan + CSR -------------------------------------------------
__global__ void k_scan1(int n) {
    __shared__ int warpsum[8];
    int base = blockIdx.x * 4096;
    int t0 = base + threadIdx.x * 16;
    int vals[16];
    int s = 0;
#pragma unroll
    for (int j = 0; j < 16; j++) {
        int idx = t0 + j;
        int v = (idx < n) ? g_deg[idx] : 0;
        vals[j] = s;
        s += v;
    }
    int lane = threadIdx.x & 31, w = threadIdx.x >> 5;
    int x = s;
#pragma unroll
    for (int d = 1; d < 32; d <<= 1) {
        int y = __shfl_up_sync(0xffffffffu, x, d);
        if (lane >= d) x += y;
    }
    if (lane == 31) warpsum[w] = x;
    __syncthreads();
    if (w == 0 && lane < 8) {
        int y = warpsum[lane];
#pragma unroll
        for (int d = 1; d < 8; d <<= 1) {
            int z = __shfl_up_sync(0xffu, y, d);
            if (lane >= d) y += z;
        }
        warpsum[lane] = y;
    }
    __syncthreads();
    int warpoff = (w > 0) ? warpsum[w - 1] : 0;
    int throff = warpoff + x - s;
#pragma unroll
    for (int j = 0; j < 16; j++) {
        int idx = t0 + j;
        if (idx < n) g_rowptr[idx] = throff + vals[j];
    }
    if (threadIdx.x == 255) g_bsums[blockIdx.x] = warpoff + x;
}
__global__ void k_scan2(int nb) {
    if (threadIdx.x == 0 && blockIdx.x == 0) {
        int s = 0;
        for (int i = 0; i < nb; i++) { int v = g_bsums[i]; g_bsums[i] = s; s += v; }
    }
}
__global__ void k_scan3(int n, int E) {
    int i = blockIdx.x * blockDim.x + threadIdx.x;
    if (i < n) {
        int r = g_rowptr[i] + g_bsums[i >> 12];
        g_rowptr[i] = r;
        g_cursor[i] = r;
    }
    if (i == 0) g_rowptr[n] = E;
}
__global__ void k_fill(const int* __restrict__ ei, int E, int n) {
    int i = blockIdx.x * blockDim.x + threadIdx.x;
    if (i < E) {
        int dst = ei[E + i];
        int src = ei[i];
        if ((unsigned)dst < (unsigned)n && (unsigned)src < (unsigned)n) {
            int pos = atomicAdd(&g_cursor[dst], 1);
            g_csr[pos] = src;
        }
    }
}

// ---------------- GEMM1: mma.sync bf16 3-split, cp.async X pipeline ----------
// X raw fp32 -> 3-slot smem ring via cp.async (prefetch distance 2) so DRAM
// latency (~550cyc) is covered by 2 iterations of slack. B hi/lo streamed in
// the SAME commit group. A bf16 tile single-buffered (2 syncs/iter).
#define X_ROW  64
#define XCH    8192                 /* 128 rows * 64B raw fp32 chunk */
#define A_ROW  48
#define ASZ    6144
#define B_ROW  48
#define BCH    6144
#define SM_TOTAL (3*XCH + 6*BCH + 2*ASZ)   /* 24576+36864+12288 = 73728 */

__global__ void __launch_bounds__(256) k_gemm1(const float* __restrict__ X, int M) {
    extern __shared__ char sm[];
    unsigned sb = smem_u32(sm);
    const unsigned Xs = sb;
    const unsigned Bh = sb + 3 * XCH;
    const unsigned Bl = Bh + 3 * BCH;
    const unsigned Ah = Bl + 3 * BCH;
    const unsigned Al = Ah + ASZ;
    const unsigned XOFF = 3 * XCH;   // byte offset of Bh within sm[] for pointers

    int tid = threadIdx.x, lane = tid & 31, wid = tid >> 5;
    int wm = wid >> 2, wn = wid & 3;
    int m0 = blockIdx.x * 128;

    float acc[4][4][4];
#pragma unroll
    for (int i = 0; i < 4; i++)
#pragma unroll
        for (int j = 0; j < 4; j++)
#pragma unroll
            for (int q = 0; q < 4; q++) acc[i][j][q] = 0.f;

    int mrow = tid >> 1, khalf = tid & 1;
    int gm = m0 + mrow;
    bool ok = gm < M;
    // X cp.async: thread covers row mrow, bytes khalf*32..+31 of each 64B chunk
    const char* xsrc = (const char*)(X + (size_t)gm * F0) + khalf * 32;
    unsigned xdst = Xs + (unsigned)(mrow * X_ROW + khalf * 32);

    int br = tid >> 1, bhx = tid & 1;
    const uint32_t* srcH = g_Wh + (size_t)br * 8 + bhx * 4;
    const uint32_t* srcL = g_Wl + (size_t)br * 8 + bhx * 4;
    unsigned dstB = (unsigned)(br * B_ROW + bhx * 16);

    // prologue: commit groups for chunks 0 and 1
#pragma unroll
    for (int c = 0; c < 2; c++) {
        size_t cofs = (size_t)c * 1024;     // 128*8 uints per chunk
        cp_async16(Bh + c * BCH + dstB, srcH + cofs);
        cp_async16(Bl + c * BCH + dstB, srcL + cofs);
        if (ok) {
            cp_async16(xdst + c * XCH, xsrc + (size_t)c * 64);
            cp_async16(xdst + c * XCH + 16, xsrc + (size_t)c * 64 + 16);
        }
        cp_commit();
    }

    int arow = (lane & 7) + ((lane >> 3) & 1) * 8;
    int acol = ((lane >> 4) & 1) * 16;
    int brow = lane & 7;
    int bsel = ((lane >> 3) & 1) * 16;

#pragma unroll 1
    for (int it = 0; it < 16; it++) {
        int slot = it % 3;
        if (it < 14) {
            int c = it + 2, cs = c % 3;
            size_t cofs = (size_t)c * 1024;
            cp_async16(Bh + cs * BCH + dstB, srcH + cofs);
            cp_async16(Bl + cs * BCH + dstB, srcL + cofs);
            if (ok) {
                cp_async16(xdst + cs * XCH, xsrc + (size_t)c * 64);
                cp_async16(xdst + cs * XCH + 16, xsrc + (size_t)c * 64 + 16);
            }
            cp_commit();
            cp_wait2();
        } else if (it == 14) {
            cp_wait1();
        } else {
            cp_wait0();
        }
        __syncthreads();
        // convert X chunk it (smem raw fp32) -> bf16 hi/lo A tile
        {
            const char* xb = sm + slot * XCH + mrow * X_ROW + khalf * 32;
            float4 va = *(const float4*)xb;
            float4 vb = *(const float4*)(xb + 16);
            float vf[8] = {va.x, va.y, va.z, va.w, vb.x, vb.y, vb.z, vb.w};
            uint32_t hu[4], lu[4];
#pragma unroll
            for (int p = 0; p < 4; p++) {
                float a = vf[2 * p], b = vf[2 * p + 1];
                __nv_bfloat16 ha = __float2bfloat16(a), hb = __float2bfloat16(b);
                hu[p] = bfpair(__bfloat162float(ha), __bfloat162float(hb));
                lu[p] = bfpair(a - __bfloat162float(ha), b - __bfloat162float(hb));
            }
            size_t off = (size_t)XOFF + 6 * BCH + mrow * A_ROW + khalf * 16;
            *(uint4*)(sm + off)       = make_uint4(hu[0], hu[1], hu[2], hu[3]);
            *(uint4*)(sm + off + ASZ) = make_uint4(lu[0], lu[1], lu[2], lu[3]);
        }
        __syncthreads();
        unsigned BhB = Bh + slot * BCH, BlB = Bl + slot * BCH;
        uint32_t ah[4][4], al[4][4], bhf[4][2], blf[4][2];
#pragma unroll
        for (int ti = 0; ti < 4; ti++) {
            unsigned o = (wm * 64 + ti * 16 + arow) * A_ROW + acol;
            ldmx4(ah[ti], Ah + o);
            ldmx4(al[ti], Al + o);
        }
#pragma unroll
        for (int tj = 0; tj < 4; tj++) {
            unsigned o = (wn * 32 + tj * 8 + brow) * B_ROW + bsel;
            ldmx2(bhf[tj], BhB + o);
            ldmx2(blf[tj], BlB + o);
        }
#pragma unroll
        for (int ti = 0; ti < 4; ti++)
#pragma unroll
            for (int tj = 0; tj < 4; tj++) {
                mma_bf16(acc[ti][tj], ah[ti], bhf[tj]);
                mma_bf16(acc[ti][tj], ah[ti], blf[tj]);
                mma_bf16(acc[ti][tj], al[ti], bhf[tj]);
            }
    }

#pragma unroll
    for (int ti = 0; ti < 4; ti++) {
#pragma unroll
        for (int tj = 0; tj < 4; tj++) {
            int mA = wm * 64 + ti * 16 + (lane >> 2);
            int nn = wn * 32 + tj * 8 + (lane & 3) * 2;
            int r0 = m0 + mA, r1 = r0 + 8;
            if (r0 < M) {
                float s = dinv_of(r0);
                g_h1h[(size_t)r0 * 64 + (nn >> 1)] =
                    pack_h2(acc[ti][tj][0] * s, acc[ti][tj][1] * s);
            }
            if (r1 < M) {
                float s = dinv_of(r1);
                g_h1h[(size_t)r1 * 64 + (nn >> 1)] =
                    pack_h2(acc[ti][tj][2] * s, acc[ti][tj][3] * s);
            }
        }
    }
}

// ---------------- Agg1 (half2 gather, fp32 accum) + fused GEMM2 (R12) --------
__global__ void __launch_bounds__(256) k_agg1(
    const float* __restrict__ b1, const float* __restrict__ W2, int n) {
    __shared__ float Wt[F2][F1];
    for (int idx = threadIdx.x; idx < (F1 * F2) / 4; idx += 256) {
        int k = idx >> 2;
        int q4 = (idx & 3) * 4;
        float4 v = *(const float4*)(W2 + (size_t)k * F2 + q4);
        Wt[q4 + 0][k] = v.x;
        Wt[q4 + 1][k] = v.y;
        Wt[q4 + 2][k] = v.z;
        Wt[q4 + 3][k] = v.w;
    }
    __syncthreads();

    int warp = (blockIdx.x * blockDim.x + threadIdx.x) >> 5;
    int lane = threadIdx.x & 31;
    if (warp >= n) return;
    int i = warp;
    int beg = g_rowptr[i], end = g_rowptr[i + 1];
    const unsigned* hs = g_h1h;
    float4 acc0, acc1 = make_float4(0.f, 0.f, 0.f, 0.f);
    {
        uint2 u = *(const uint2*)(hs + (size_t)i * 64 + lane * 2);
        float2 a = __half22float2(*(__half2*)&u.x);
        float2 b = __half22float2(*(__half2*)&u.y);
        acc0 = make_float4(a.x, a.y, b.x, b.y);
    }
    for (int e = beg; e < end; e += 32) {
        int cnt = min(32, end - e);
        int j = (e + lane < end) ? g_csr[e + lane] : 0;
        int t = 0;
        for (; t + 1 < cnt; t += 2) {
            int j0 = __shfl_sync(0xffffffffu, j, t);
            int j1 = __shfl_sync(0xffffffffu, j, t + 1);
            uint2 u0 = *(const uint2*)(hs + (size_t)j0 * 64 + lane * 2);
            uint2 u1 = *(const uint2*)(hs + (size_t)j1 * 64 + lane * 2);
            float2 a0 = __half22float2(*(__half2*)&u0.x);
            float2 b0 = __half22float2(*(__half2*)&u0.y);
            float2 a1 = __half22float2(*(__half2*)&u1.x);
            float2 b1 = __half22float2(*(__half2*)&u1.y);
            acc0.x += a0.x; acc0.y += a0.y; acc0.z += b0.x; acc0.w += b0.y;
            acc1.x += a1.x; acc1.y += a1.y; acc1.z += b1.x; acc1.w += b1.y;
        }
        if (t < cnt) {
            int j0 = __shfl_sync(0xffffffffu, j, t);
            uint2 u0 = *(const uint2*)(hs + (size_t)j0 * 64 + lane * 2);
            float2 a0 = __half22float2(*(__half2*)&u0.x);
            float2 b0 = __half22float2(*(__half2*)&u0.y);
            acc0.x += a0.x; acc0.y += a0.y; acc0.z += b0.x; acc0.w += b0.y;
        }
    }
    float s = dinv_of(i);
    float4 bb = *(const float4*)(b1 + lane * 4);
    float f[4];
    f[0] = fmaxf(fmaf(acc0.x + acc1.x, s, bb.x), 0.f);
    f[1] = fmaxf(fmaf(acc0.y + acc1.y, s, bb.y), 0.f);
    f[2] = fmaxf(fmaf(acc0.z + acc1.z, s, bb.z), 0.f);
    f[3] = fmaxf(fmaf(acc0.w + acc1.w, s, bb.w), 0.f);

    float p[F2];
#pragma unroll
    for (int q = 0; q < F2; q++) {
        float4 w = *(const float4*)(&Wt[q][lane * 4]);
        p[q] = f[0] * w.x + f[1] * w.y + f[2] * w.z + f[3] * w.w;
    }
#pragma unroll
    for (int d = 16; d >= 1; d >>= 1) {
#pragma unroll
        for (int q = 0; q < F2; q++)
            p[q] += __shfl_xor_sync(0xffffffffu, p[q], d);
    }
    if (lane < 4) {
        float4 v = make_float4(p[lane * 4] * s, p[lane * 4 + 1] * s,
                               p[lane * 4 + 2] * s, p[lane * 4 + 3] * s);
        *(float4*)(g_h2 + (size_t)i * F2 + lane * 4) = v;
    }
}

// ---------------- Agg2: 4 threads per node, 16 dims, + b2 (R12) --------------
__global__ void k_agg2(const float* __restrict__ b2, float* __restrict__ out, int n) {
    int gt = blockIdx.x * blockDim.x + threadIdx.x;
    int i = gt >> 2;
    if (i >= n) return;
    int q = (gt & 3) * 4;
    int beg = g_rowptr[i], end = g_rowptr[i + 1];
    const float* hs = g_h2;
    float4 acc = *(const float4*)(hs + (size_t)i * F2 + q);
    for (int e = beg; e < end; e++) {
        int j = g_csr[e];
        float4 v = *(const float4*)(hs + (size_t)j * F2 + q);
        acc.x += v.x; acc.y += v.y; acc.z += v.z; acc.w += v.w;
    }
    float s = dinv_of(i);
    float4 bb = *(const float4*)(b2 + q);
    float4 r = make_float4(fmaf(acc.x, s, bb.x), fmaf(acc.y, s, bb.y),
                           fmaf(acc.z, s, bb.z), fmaf(acc.w, s, bb.w));
    *(float4*)(out + (size_t)i * F2 + q) = r;
}

// ---------------- launch: fork/join graph ------------------------------------
extern "C" void kernel_launch(void* const* d_in, const int* in_sizes, int n_in,
                              void* d_out, int out_size) {
    const float* x  = (const float*)d_in[0];
    const int*   ei = (const int*)d_in[1];
    const float* W1 = (const float*)d_in[2];
    const float* b1 = (const float*)d_in[3];
    const float* W2 = (const float*)d_in[4];
    const float* b2 = (const float*)d_in[5];
    float* out = (float*)d_out;

    int n = in_sizes[0] / F0;       // 100000
    int E = in_sizes[1] / 2;        // 1600000

    static cudaStream_t s2 = 0;
    static cudaEvent_t evFork = 0, evJoin = 0;
    if (!s2) {
        cudaStreamCreateWithFlags(&s2, cudaStreamNonBlocking);
        cudaEventCreateWithFlags(&evFork, cudaEventDisableTiming);
        cudaEventCreateWithFlags(&evJoin, cudaEventDisableTiming);
        cudaFuncSetAttribute(k_gemm1, cudaFuncAttributeMaxDynamicSharedMemorySize,
                             SM_TOTAL);
    }

    int tb = 256;
    k_prepw<<<8, 256>>>(W1);                       // launch 1
    k_zero<<<(n + tb - 1) / tb, tb>>>(n);          // launch 2
    k_deg<<<(E + tb - 1) / tb, tb>>>(ei, E, n);    // launch 3

    cudaEventRecord(evFork, 0);
    cudaStreamWaitEvent(s2, evFork, 0);

    k_gemm1<<<(n + 127) / 128, 256, SM_TOTAL>>>(x, n);   // launch 4 (sampled)

    int nb = (n + 4095) / 4096;
    k_scan1<<<nb, 256, 0, s2>>>(n);
    k_scan2<<<1, 32, 0, s2>>>(nb);
    k_scan3<<<(n + tb - 1) / tb, tb, 0, s2>>>(n, E);
    k_fill<<<(E + tb - 1) / tb, tb, 0, s2>>>(ei, E, n);
    cudaEventRecord(evJoin, s2);

    cudaStreamWaitEvent(0, evJoin, 0);
    k_agg1<<<(n * 32 + tb - 1) / tb, tb>>>(b1, W2, n);
    k_agg2<<<(n * 4 + tb - 1) / tb, tb>>>(b2, out, n);
}

// round 15
// speedup vs baseline: 1.0935x; 1.0807x over previous
#include <cuda_runtime.h>
#include <cuda_bf16.h>
#include <cuda_fp16.h>
#include <math.h>
#include <cstdint>

#define N_MAX 100000
#define E_MAX 1600000
#define F0 256
#define F1 128
#define F2 16

// ---------------- scratch (static device globals; no allocation) ------------
__device__ int      g_deg[N_MAX];
__device__ int      g_rowptr[N_MAX + 1];
__device__ int      g_cursor[N_MAX];
__device__ int      g_csr[E_MAX];
__device__ unsigned g_h1h[(size_t)N_MAX * F1 / 2];  // h1 as half2 pairs
__device__ float    g_h2[(size_t)N_MAX * F2];
__device__ int      g_bsums[64];
// W1 as fp16, chunked [16 kchunks][128 n][4 uints (16 k fp16)]
__device__ uint32_t g_Wf[16 * 128 * 4];

// ---------------- helpers ----------------------------------------------------
__device__ __forceinline__ unsigned smem_u32(const void* p) {
    unsigned r;
    asm("{ .reg .u64 t; cvta.to.shared.u64 t, %1; cvt.u32.u64 %0, t; }"
        : "=r"(r) : "l"(p));
    return r;
}
__device__ __forceinline__ void cp_async16(unsigned dst, const void* src) {
    asm volatile("cp.async.ca.shared.global [%0], [%1], 16;"
                 :: "r"(dst), "l"(src));
}
__device__ __forceinline__ void cp_commit() { asm volatile("cp.async.commit_group;"); }
__device__ __forceinline__ void cp_wait0()  { asm volatile("cp.async.wait_group 0;"); }
__device__ __forceinline__ unsigned pack_h2(float a, float b) {
    __half2 h = __floats2half2_rn(a, b);
    return *(unsigned*)&h;
}
__device__ __forceinline__ void ldmx4(uint32_t* r, unsigned addr) {
    asm volatile("ldmatrix.sync.aligned.m8n8.x4.shared.b16 {%0,%1,%2,%3}, [%4];"
                 : "=r"(r[0]), "=r"(r[1]), "=r"(r[2]), "=r"(r[3]) : "r"(addr));
}
__device__ __forceinline__ void ldmx2(uint32_t* r, unsigned addr) {
    asm volatile("ldmatrix.sync.aligned.m8n8.x2.shared.b16 {%0,%1}, [%2];"
                 : "=r"(r[0]), "=r"(r[1]) : "r"(addr));
}
__device__ __forceinline__ void mma_f16(float* d, const uint32_t* a, const uint32_t* b) {
    asm volatile(
        "mma.sync.aligned.m16n8k16.row.col.f32.f16.f16.f32 "
        "{%0,%1,%2,%3}, {%4,%5,%6,%7}, {%8,%9}, {%0,%1,%2,%3};"
        : "+f"(d[0]), "+f"(d[1]), "+f"(d[2]), "+f"(d[3])
        : "r"(a[0]), "r"(a[1]), "r"(a[2]), "r"(a[3]), "r"(b[0]), "r"(b[1]));
}
__device__ __forceinline__ float dinv_of(int i) {
    return rsqrtf((float)(g_deg[i] + 1));
}

// ---------------- small kernels ----------------------------------------------
__global__ void k_zero(int n) {
    int i = blockIdx.x * blockDim.x + threadIdx.x;
    if (i < n) g_deg[i] = 0;
}
__global__ void k_deg(const int* __restrict__ ei, int E, int n) {
    int i = blockIdx.x * blockDim.x + threadIdx.x;
    if (i < E) {
        int dst = ei[E + i];
        if ((unsigned)dst < (unsigned)n) atomicAdd(&g_deg[dst], 1);
    }
}

// W1 [256][128] fp32 -> fp16 chunks [c][nn][4u]
__global__ void k_prepw(const float* __restrict__ W) {
    int idx = blockIdx.x * blockDim.x + threadIdx.x;
    if (idx >= 16 * 128) return;
    int c = idx >> 7;
    int nn = idx & 127;
    uint32_t hu[4];
#pragma unroll
    for (int p = 0; p < 4; p++) {
        float v0 = W[(size_t)(c * 16 + 4 * p) * F1 + nn];
        float v1 = W[(size_t)(c * 16 + 4 * p + 1) * F1 + nn];
        float v2 = W[(size_t)(c * 16 + 4 * p + 2) * F1 + nn];
        float v3 = W[(size_t)(c * 16 + 4 * p + 3) * F1 + nn];
        // pack consecutive k pairs
        hu[p] = 0;  // placeholder (rewritten below)
        (void)v2; (void)v3;
        // actually need pairs (2p,2p+1): rewrite properly below
    }
    // proper packing: 16 k-values -> 8 half2 pairs -> but tile row is 16 fp16
    // = 8 uints? No: 16 fp16 = 32B = 8 half2? 16 halves = 8 uint32.
    // Layout row: k0..k15 as fp16 -> 8 uints. Chunk stride = 128*8? We sized
    // g_Wf as [16][128][4]... fix: store as 8 uints per row is needed.
    // -- handled by second kernel variant below --
    (void)hu;
}

// Correct W prep: row = 16 fp16 = 8 uints... but g_Wf has 4 uints/row slots.
// Use half2 packing: 16 halves = 8 uint32. Resize via flat indexing into g_Wf
// is impossible (4/row). Instead: k16 chunk row holds 16 fp16 = 32 bytes = 8
// uints. g_Wf must be 16*128*8. Redeclare usage accordingly.
__device__ uint32_t g_Wf8[16 * 128 * 8];

__global__ void k_prepw2(const float* __restrict__ W) {
    int idx = blockIdx.x * blockDim.x + threadIdx.x;
    if (idx >= 16 * 128) return;
    int c = idx >> 7;
    int nn = idx & 127;
    uint32_t u[8];
#pragma unroll
    for (int p = 0; p < 8; p++) {
        float v0 = W[(size_t)(c * 16 + 2 * p) * F1 + nn];
        float v1 = W[(size_t)(c * 16 + 2 * p + 1) * F1 + nn];
        u[p] = pack_h2(v0, v1);
    }
    uint32_t* d = g_Wf8 + (size_t)idx * 8;
    *(uint4*)(d)     = make_uint4(u[0], u[1], u[2], u[3]);
    *(uint4*)(d + 4) = make_uint4(u[4], u[5], u[6], u[7]);
}

// ---------------- scan + CSR -------------------------------------------------
__global__ void k_scan1(int n) {
    __shared__ int warpsum[8];
    int base = blockIdx.x * 4096;
    int t0 = base + threadIdx.x * 16;
    int vals[16];
    int s = 0;
#pragma unroll
    for (int j = 0; j < 16; j++) {
        int idx = t0 + j;
        int v = (idx < n) ? g_deg[idx] : 0;
        vals[j] = s;
        s += v;
    }
    int lane = threadIdx.x & 31, w = threadIdx.x >> 5;
    int x = s;
#pragma unroll
    for (int d = 1; d < 32; d <<= 1) {
        int y = __shfl_up_sync(0xffffffffu, x, d);
        if (lane >= d) x += y;
    }
    if (lane == 31) warpsum[w] = x;
    __syncthreads();
    if (w == 0 && lane < 8) {
        int y = warpsum[lane];
#pragma unroll
        for (int d = 1; d < 8; d <<= 1) {
            int z = __shfl_up_sync(0xffu, y, d);
            if (lane >= d) y += z;
        }
        warpsum[lane] = y;
    }
    __syncthreads();
    int warpoff = (w > 0) ? warpsum[w - 1] : 0;
    int throff = warpoff + x - s;
#pragma unroll
    for (int j = 0; j < 16; j++) {
        int idx = t0 + j;
        if (idx < n) g_rowptr[idx] = throff + vals[j];
    }
    if (threadIdx.x == 255) g_bsums[blockIdx.x] = warpoff + x;
}
__global__ void k_scan2(int nb) {
    if (threadIdx.x == 0 && blockIdx.x == 0) {
        int s = 0;
        for (int i = 0; i < nb; i++) { int v = g_bsums[i]; g_bsums[i] = s; s += v; }
    }
}
__global__ void k_scan3(int n, int E) {
    int i = blockIdx.x * blockDim.x + threadIdx.x;
    if (i < n) {
        int r = g_rowptr[i] + g_bsums[i >> 12];
        g_rowptr[i] = r;
        g_cursor[i] = r;
    }
    if (i == 0) g_rowptr[n] = E;
}
__global__ void k_fill(const int* __restrict__ ei, int E, int n) {
    int i = blockIdx.x * blockDim.x + threadIdx.x;
    if (i < E) {
        int dst = ei[E + i];
        int src = ei[i];
        if ((unsigned)dst < (unsigned)n && (unsigned)src < (unsigned)n) {
            int pos = atomicAdd(&g_cursor[dst], 1);
            g_csr[pos] = src;
        }
    }
}

// ---------------- GEMM1: single-term fp16 mma.sync, streamed B (R12 shape) ---
#define A_ROW  48
#define ASZ    6144                 /* 128 rows * 48B */
#define B_ROW  48
#define BCH    6144
#define SM_TOTAL (2*BCH + 2*ASZ)    /* 24576 */

__global__ void __launch_bounds__(256) k_gemm1(const float* __restrict__ X, int M) {
    extern __shared__ char sm[];
    unsigned sb = smem_u32(sm);
    const unsigned Bs = sb, Ab = sb + 2 * BCH;

    int tid = threadIdx.x, lane = tid & 31, wid = tid >> 5;
    int wm = wid >> 2, wn = wid & 3;
    int m0 = blockIdx.x * 128;

    float acc[4][4][4];
#pragma unroll
    for (int i = 0; i < 4; i++)
#pragma unroll
        for (int j = 0; j < 4; j++)
#pragma unroll
            for (int q = 0; q < 4; q++) acc[i][j][q] = 0.f;

    int mrow = tid >> 1, khalf = tid & 1;
    int gm = m0 + mrow;
    bool ok = gm < M;
    const float4 z4 = make_float4(0.f, 0.f, 0.f, 0.f);
    const float* xrow = X + (size_t)gm * F0 + khalf * 8;

    int br = tid >> 1, bhx = tid & 1;
    const uint32_t* srcW = g_Wf8 + (size_t)br * 8 + bhx * 4;
    unsigned dstB = (unsigned)(br * B_ROW + bhx * 16);

    // stage chunk 0
    cp_async16(Bs + dstB, srcW);
    cp_commit();
    {
        float4 va = ok ? *(const float4*)(xrow)     : z4;
        float4 vb = ok ? *(const float4*)(xrow + 4) : z4;
        uint4 pk = make_uint4(pack_h2(va.x, va.y), pack_h2(va.z, va.w),
                              pack_h2(vb.x, vb.y), pack_h2(vb.z, vb.w));
        *(uint4*)(sm + (size_t)(2 * BCH) + mrow * A_ROW + khalf * 16) = pk;
    }
    cp_wait0();
    __syncthreads();

    int arow = (lane & 7) + ((lane >> 3) & 1) * 8;
    int acol = ((lane >> 4) & 1) * 16;
    int brow = lane & 7;
    int bsel = ((lane >> 3) & 1) * 16;

#pragma unroll 1
    for (int it = 0; it < 16; it++) {
        int cur = it & 1, nxt = cur ^ 1;
        float4 na = z4, nb = z4;
        if (it < 15) {
            size_t cofs = (size_t)(it + 1) * 128 * 8;
            cp_async16(Bs + nxt * BCH + dstB, srcW + cofs);
            cp_commit();
            const float* xc = xrow + (it + 1) * 16;
            na = ok ? *(const float4*)(xc)     : z4;
            nb = ok ? *(const float4*)(xc + 4) : z4;
        }
        unsigned AB = Ab + cur * ASZ, BB = Bs + cur * BCH;
        uint32_t a[4][4], b[4][2];
#pragma unroll
        for (int ti = 0; ti < 4; ti++) {
            unsigned o = (wm * 64 + ti * 16 + arow) * A_ROW + acol;
            ldmx4(a[ti], AB + o);
        }
#pragma unroll
        for (int tj = 0; tj < 4; tj++) {
            unsigned o = (wn * 32 + tj * 8 + brow) * B_ROW + bsel;
            ldmx2(b[tj], BB + o);
        }
#pragma unroll
        for (int ti = 0; ti < 4; ti++)
#pragma unroll
            for (int tj = 0; tj < 4; tj++)
                mma_f16(acc[ti][tj], a[ti], b[tj]);
        if (it < 15) {
            uint4 pk = make_uint4(pack_h2(na.x, na.y), pack_h2(na.z, na.w),
                                  pack_h2(nb.x, nb.y), pack_h2(nb.z, nb.w));
            *(uint4*)(sm + (size_t)(2 * BCH) + nxt * ASZ + mrow * A_ROW + khalf * 16) = pk;
            cp_wait0();
        }
        __syncthreads();
    }

#pragma unroll
    for (int ti = 0; ti < 4; ti++) {
#pragma unroll
        for (int tj = 0; tj < 4; tj++) {
            int mA = wm * 64 + ti * 16 + (lane >> 2);
            int nn = wn * 32 + tj * 8 + (lane & 3) * 2;
            int r0 = m0 + mA, r1 = r0 + 8;
            if (r0 < M) {
                float s = dinv_of(r0);
                g_h1h[(size_t)r0 * 64 + (nn >> 1)] =
                    pack_h2(acc[ti][tj][0] * s, acc[ti][tj][1] * s);
            }
            if (r1 < M) {
                float s = dinv_of(r1);
                g_h1h[(size_t)r1 * 64 + (nn >> 1)] =
                    pack_h2(acc[ti][tj][2] * s, acc[ti][tj][3] * s);
            }
        }
    }
}

// ---------------- Agg1 (half2 gather, fp32 accum) + fused GEMM2 --------------
__global__ void __launch_bounds__(256) k_agg1(
    const float* __restrict__ b1, const float* __restrict__ W2, int n) {
    __shared__ float Wt[F2][F1];
    for (int idx = threadIdx.x; idx < (F1 * F2) / 4; idx += 256) {
        int k = idx >> 2;
        int q4 = (idx & 3) * 4;
        float4 v = *(const float4*)(W2 + (size_t)k * F2 + q4);
        Wt[q4 + 0][k] = v.x;
        Wt[q4 + 1][k] = v.y;
        Wt[q4 + 2][k] = v.z;
        Wt[q4 + 3][k] = v.w;
    }
    __syncthreads();

    int warp = (blockIdx.x * blockDim.x + threadIdx.x) >> 5;
    int lane = threadIdx.x & 31;
    if (warp >= n) return;
    int i = warp;
    int beg = g_rowptr[i], end = g_rowptr[i + 1];
    const unsigned* hs = g_h1h;
    float4 acc0, acc1 = make_float4(0.f, 0.f, 0.f, 0.f);
    {
        uint2 u = *(const uint2*)(hs + (size_t)i * 64 + lane * 2);
        float2 a = __half22float2(*(__half2*)&u.x);
        float2 b = __half22float2(*(__half2*)&u.y);
        acc0 = make_float4(a.x, a.y, b.x, b.y);
    }
    for (int e = beg; e < end; e += 32) {
        int cnt = min(32, end - e);
        int j = (e + lane < end) ? g_csr[e + lane] : 0;
        int t = 0;
        for (; t + 1 < cnt; t += 2) {
            int j0 = __shfl_sync(0xffffffffu, j, t);
            int j1 = __shfl_sync(0xffffffffu, j, t + 1);
            uint2 u0 = *(const uint2*)(hs + (size_t)j0 * 64 + lane * 2);
            uint2 u1 = *(const uint2*)(hs + (size_t)j1 * 64 + lane * 2);
            float2 a0 = __half22float2(*(__half2*)&u0.x);
            float2 b0 = __half22float2(*(__half2*)&u0.y);
            float2 a1 = __half22float2(*(__half2*)&u1.x);
            float2 b1 = __half22float2(*(__half2*)&u1.y);
            acc0.x += a0.x; acc0.y += a0.y; acc0.z += b0.x; acc0.w += b0.y;
            acc1.x += a1.x; acc1.y += a1.y; acc1.z += b1.x; acc1.w += b1.y;
        }
        if (t < cnt) {
            int j0 = __shfl_sync(0xffffffffu, j, t);
            uint2 u0 = *(const uint2*)(hs + (size_t)j0 * 64 + lane * 2);
            float2 a0 = __half22float2(*(__half2*)&u0.x);
            float2 b0 = __half22float2(*(__half2*)&u0.y);
            acc0.x += a0.x; acc0.y += a0.y; acc0.z += b0.x; acc0.w += b0.y;
        }
    }
    float s = dinv_of(i);
    float4 bb = *(const float4*)(b1 + lane * 4);
    float f[4];
    f[0] = fmaxf(fmaf(acc0.x + acc1.x, s, bb.x), 0.f);
    f[1] = fmaxf(fmaf(acc0.y + acc1.y, s, bb.y), 0.f);
    f[2] = fmaxf(fmaf(acc0.z + acc1.z, s, bb.z), 0.f);
    f[3] = fmaxf(fmaf(acc0.w + acc1.w, s, bb.w), 0.f);

    float p[F2];
#pragma unroll
    for (int q = 0; q < F2; q++) {
        float4 w = *(const float4*)(&Wt[q][lane * 4]);
        p[q] = f[0] * w.x + f[1] * w.y + f[2] * w.z + f[3] * w.w;
    }
#pragma unroll
    for (int d = 16; d >= 1; d >>= 1) {
#pragma unroll
        for (int q = 0; q < F2; q++)
            p[q] += __shfl_xor_sync(0xffffffffu, p[q], d);
    }
    if (lane < 4) {
        float4 v = make_float4(p[lane * 4] * s, p[lane * 4 + 1] * s,
                               p[lane * 4 + 2] * s, p[lane * 4 + 3] * s);
        *(float4*)(g_h2 + (size_t)i * F2 + lane * 4) = v;
    }
}

// ---------------- Agg2: 4 threads per node, 16 dims, + b2 -------------------
__global__ void k_agg2(const float* __restrict__ b2, float* __restrict__ out, int n) {
    int gt = blockIdx.x * blockDim.x + threadIdx.x;
    int i = gt >> 2;
    if (i >= n) return;
    int q = (gt & 3) * 4;
    int beg = g_rowptr[i], end = g_rowptr[i + 1];
    const float* hs = g_h2;
    float4 acc = *(const float4*)(hs + (size_t)i * F2 + q);
    for (int e = beg; e < end; e++) {
        int j = g_csr[e];
        float4 v = *(const float4*)(hs + (size_t)j * F2 + q);
        acc.x += v.x; acc.y += v.y; acc.z += v.z; acc.w += v.w;
    }
    float s = dinv_of(i);
    float4 bb = *(const float4*)(b2 + q);
    float4 r = make_float4(fmaf(acc.x, s, bb.x), fmaf(acc.y, s, bb.y),
                           fmaf(acc.z, s, bb.z), fmaf(acc.w, s, bb.w));
    *(float4*)(out + (size_t)i * F2 + q) = r;
}

// ---------------- launch: fork/join graph ------------------------------------
extern "C" void kernel_launch(void* const* d_in, const int* in_sizes, int n_in,
                              void* d_out, int out_size) {
    const float* x  = (const float*)d_in[0];
    const int*   ei = (const int*)d_in[1];
    const float* W1 = (const float*)d_in[2];
    const float* b1 = (const float*)d_in[3];
    const float* W2 = (const float*)d_in[4];
    const float* b2 = (const float*)d_in[5];
    float* out = (float*)d_out;

    int n = in_sizes[0] / F0;       // 100000
    int E = in_sizes[1] / 2;        // 1600000

    static cudaStream_t s2 = 0;
    static cudaEvent_t evFork = 0, evJoin = 0;
    if (!s2) {
        cudaStreamCreateWithFlags(&s2, cudaStreamNonBlocking);
        cudaEventCreateWithFlags(&evFork, cudaEventDisableTiming);
        cudaEventCreateWithFlags(&evJoin, cudaEventDisableTiming);
        cudaFuncSetAttribute(k_gemm1, cudaFuncAttributeMaxDynamicSharedMemorySize,
                             SM_TOTAL);
    }

    int tb = 256;
    k_prepw2<<<8, 256>>>(W1);                      // launch 1
    k_zero<<<(n + tb - 1) / tb, tb>>>(n);          // launch 2
    k_deg<<<(E + tb - 1) / tb, tb>>>(ei, E, n);    // launch 3

    cudaEventRecord(evFork, 0);
    cudaStreamWaitEvent(s2, evFork, 0);

    k_gemm1<<<(n + 127) / 128, 256, SM_TOTAL>>>(x, n);   // launch 4 (sampled)

    int nb = (n + 4095) / 4096;
    k_scan1<<<nb, 256, 0, s2>>>(n);
    k_scan2<<<1, 32, 0, s2>>>(nb);
    k_scan3<<<(n + tb - 1) / tb, tb, 0, s2>>>(n, E);
    k_fill<<<(E + tb - 1) / tb, tb, 0, s2>>>(ei, E, n);
    cudaEventRecord(evJoin, s2);

    cudaStreamWaitEvent(0, evJoin, 0);
    k_agg1<<<(n * 32 + tb - 1) / tb, tb>>>(b1, W2, n);
    k_agg2<<<(n * 4 + tb - 1) / tb, tb>>>(b2, out, n);
}